// round 15
// baseline (speedup 1.0000x reference)
#include <cuda_runtime.h>
#include <cuda_fp16.h>
#include <math.h>
#include <stdint.h>

// ---------------------------------------------------------------------------
// LinOSS layer: B=16, N=4096, q=256 on sm_103
// fp16 operands pre-converted; GEMMs: cp.async 2-stage (BK=64) HMMA.
//   u16 = fp16(u); W*16 = fp16(W*)
//   Bu16 = fp16(u16 @ WB16^T + bB)
//   y    = IM scan over Bu16 (chunked 3-pass, KS combine); y fp32 + y16
//   P16  = fp16(u16 @ WD16^T + bC + bD)       [overlapped with scan, stream 2]
//   h    = y16@WC16^T + P16; g=gelu(h); out=g*sigmoid(g)+u16
// Output: [out | y]
// ---------------------------------------------------------------------------

namespace {
constexpr int kB = 16;
constexpr int kN = 4096;
constexpr int kQ = 256;
constexpr int kM = kB * kN;                 // 65536
constexpr float kDT = 1.0f / 4096.0f;
constexpr int kNChunk = 64;
constexpr int kCLen = kN / kNChunk;         // 64

constexpr int TM = 128, TN = 128, BK = 64;  // CTA tile, K-chunk (fp16)
constexpr int SSTR = 72;                    // smem row stride in halves (144 B)
constexpr int PL_ELEMS = TM * SSTR;         // 9216
constexpr int PL_BYTES = PL_ELEMS * 2;      // 18432
constexpr int STAGE_BYTES = 2 * PL_BYTES;   // 36864 (A plane + B plane)
constexpr int SMEM_BYTES = 2 * STAGE_BYTES; // 73728 (x2 CTA = 147KB, fits)
}  // namespace

// Device scratch (static; no cudaMalloc allowed)
__device__ __half g_Bu16[(size_t)kM * kQ];
__device__ float2 g_end[kB * kNChunk * kQ];
__device__ float2 g_init[kB * kNChunk * kQ];
__device__ __half g_u16[(size_t)kM * kQ];
__device__ __half g_y16[(size_t)kM * kQ];
__device__ __half g_P16[(size_t)kM * kQ];
__device__ __half g_WB16[kQ * kQ];
__device__ __half g_WC16[kQ * kQ];
__device__ __half g_WD16[kQ * kQ];

// ---------------------------------------------------------------------------
// helpers
// ---------------------------------------------------------------------------
__device__ __forceinline__ uint32_t smem_u32(const void* p) {
    uint32_t a;
    asm("{ .reg .u64 t; cvta.to.shared.u64 t, %1; cvt.u32.u64 %0, t; }" : "=r"(a) : "l"(p));
    return a;
}
__device__ __forceinline__ uint32_t packh(float a, float b) {
    __half2 h = __floats2half2_rn(a, b);
    uint32_t u; memcpy(&u, &h, 4); return u;
}
__device__ __forceinline__ void ldsm4(uint32_t (&r)[4], uint32_t addr) {
    asm volatile("ldmatrix.sync.aligned.m8n8.x4.shared.b16 {%0,%1,%2,%3}, [%4];"
                 : "=r"(r[0]), "=r"(r[1]), "=r"(r[2]), "=r"(r[3]) : "r"(addr));
}
__device__ __forceinline__ void mma16816(float* c, const uint32_t* a, const uint32_t* b) {
    asm volatile(
        "mma.sync.aligned.m16n8k16.row.col.f32.f16.f16.f32 "
        "{%0,%1,%2,%3}, {%4,%5,%6,%7}, {%8,%9}, {%0,%1,%2,%3};"
        : "+f"(c[0]), "+f"(c[1]), "+f"(c[2]), "+f"(c[3])
        : "r"(a[0]), "r"(a[1]), "r"(a[2]), "r"(a[3]), "r"(b[0]), "r"(b[1]));
}
#define CP_COMMIT() asm volatile("cp.async.commit_group;" ::: "memory")
#define CP_WAIT0()  asm volatile("cp.async.wait_group 0;" ::: "memory")

// Issue one stage: A tile (128 x 64 fp16) + B tile (128 x 64 fp16).
__device__ __forceinline__ void cpa_stage(uint32_t sb, const __half* __restrict__ aSrc,
                                          const __half* __restrict__ bSrc, int tid) {
#pragma unroll
    for (int k = 0; k < 4; k++) {
        int t = tid + k * 256;             // 0..1023
        int r = t >> 3, j = t & 7;
        const __half* g = aSrc + (size_t)r * kQ + j * 8;
        uint32_t s = sb + (uint32_t)(r * (SSTR * 2) + j * 16);
        asm volatile("cp.async.ca.shared.global [%0], [%1], 16;" :: "r"(s), "l"(g));
    }
#pragma unroll
    for (int k = 0; k < 4; k++) {
        int t = tid + k * 256;
        int r = t >> 3, j = t & 7;
        const __half* g = bSrc + (size_t)r * kQ + j * 8;
        uint32_t s = sb + PL_BYTES + (uint32_t)(r * (SSTR * 2) + j * 16);
        asm volatile("cp.async.ca.shared.global [%0], [%1], 16;" :: "r"(s), "l"(g));
    }
}

// MMA over one resident stage: warp tile 32(M) x 64(N), 4 k16 steps.
__device__ __forceinline__ void mma_stage(uint32_t sb, float (&acc)[2][8][4],
                                          int lane, int wm, int wn) {
    const int g = lane >> 3, l = lane & 7;
#pragma unroll
    for (int k16 = 0; k16 < 4; k16++) {
        uint32_t afrag[2][4];
        const int acol = k16 * 16 + (g >> 1) * 8;
#pragma unroll
        for (int mt = 0; mt < 2; mt++) {
            const int arow = wm + mt * 16 + (g & 1) * 8 + l;
            ldsm4(afrag[mt], sb + (uint32_t)(arow * SSTR + acol) * 2);
        }
        const int bcol = k16 * 16 + (g & 1) * 8;
#pragma unroll
        for (int np = 0; np < 4; np++) {
            const int brow = wn + np * 16 + (g >> 1) * 8 + l;
            uint32_t bfrag[4];
            ldsm4(bfrag, sb + PL_BYTES + (uint32_t)(brow * SSTR + bcol) * 2);
#pragma unroll
            for (int mt = 0; mt < 2; mt++) {
#pragma unroll
                for (int nt = 0; nt < 2; nt++) {
                    mma16816(acc[mt][np * 2 + nt], afrag[mt], &bfrag[nt * 2]);
                }
            }
        }
    }
}

// Shared GEMM mainloop: C chunks of BK over A/B row-major [*, kQ] sources.
template <int C>
__device__ __forceinline__ void gemm_loop(uint32_t smb, const __half* aBase,
                                          const __half* bBase, int tid, int lane,
                                          int wm, int wn, float (&acc)[2][8][4]) {
    cpa_stage(smb, aBase, bBase, tid); CP_COMMIT();
    for (int c = 0; c < C; c++) {
        CP_WAIT0();
        __syncthreads();
        if (c + 1 < C) {
            cpa_stage(smb + ((c + 1) & 1) * STAGE_BYTES,
                      aBase + (c + 1) * BK, bBase + (c + 1) * BK, tid);
            CP_COMMIT();
        }
        mma_stage(smb + (c & 1) * STAGE_BYTES, acc, lane, wm, wn);
    }
}

// ---------------------------------------------------------------------------
// Converter: u (16M elems) + WB/WC/WD (64K each), one kernel.
// ---------------------------------------------------------------------------
__global__ __launch_bounds__(256) void k_cvt(const float* __restrict__ u,
                                             const float* __restrict__ wb,
                                             const float* __restrict__ wc,
                                             const float* __restrict__ wd) {
    const int uN = kM * kQ / 4;
    const int per = kQ * kQ / 4;
    int i = blockIdx.x * blockDim.x + threadIdx.x;
    const float* s;
    __half* d;
    int j;
    if (i < uN) { s = u; d = g_u16; j = i; }
    else {
        int w = i - uN;
        s = (w < per) ? wb : (w < 2 * per ? wc : wd);
        d = (w < per) ? g_WB16 : (w < 2 * per ? g_WC16 : g_WD16);
        j = w % per;
    }
    float4 v = reinterpret_cast<const float4*>(s)[j];
    uint2 o; o.x = packh(v.x, v.y); o.y = packh(v.z, v.w);
    reinterpret_cast<uint2*>(d)[j] = o;
}

// ---------------------------------------------------------------------------
// GEMM1: g_Bu16 = fp16(u16 @ WB16^T + bias)
// ---------------------------------------------------------------------------
__global__ __launch_bounds__(256, 2) void k_mm_bu(const float* __restrict__ bias)
{
    extern __shared__ __half smem[];
    const int tid = threadIdx.x;
    const int bn = blockIdx.x, bm = blockIdx.y;
    const int tileRow = bm * TM;
    const int lane = tid & 31, wid = tid >> 5;
    const int wm = (wid & 3) * 32, wn = (wid >> 2) * 64;
    const uint32_t smb = smem_u32(smem);

    float acc[2][8][4];
#pragma unroll
    for (int a = 0; a < 2; a++)
#pragma unroll
        for (int b = 0; b < 8; b++)
#pragma unroll
            for (int c = 0; c < 4; c++) acc[a][b][c] = 0.0f;

    gemm_loop<kQ / BK>(smb, g_u16 + (size_t)tileRow * kQ,
                       g_WB16 + (size_t)bn * TN * kQ, tid, lane, wm, wn, acc);

    const int r0 = tileRow + wm + (lane >> 2);
    const int cb = bn * TN + wn;
#pragma unroll
    for (int mt = 0; mt < 2; mt++) {
        const int rr = r0 + mt * 16;
#pragma unroll
        for (int nt = 0; nt < 8; nt++) {
            const int cc = cb + nt * 8 + (lane & 3) * 2;
            const float b0 = bias[cc], b1 = bias[cc + 1];
            uint32_t lo = packh(acc[mt][nt][0] + b0, acc[mt][nt][1] + b1);
            uint32_t hi = packh(acc[mt][nt][2] + b0, acc[mt][nt][3] + b1);
            *reinterpret_cast<uint32_t*>(&g_Bu16[(size_t)rr * kQ + cc]) = lo;
            *reinterpret_cast<uint32_t*>(&g_Bu16[(size_t)(rr + 8) * kQ + cc]) = hi;
        }
    }
}

// ---------------------------------------------------------------------------
// GEMM-UD: g_P16 = fp16(u16 @ WD16^T + bC + bD)    [runs overlapped w/ scan]
// ---------------------------------------------------------------------------
__global__ __launch_bounds__(256, 2) void k_mm_ud(const float* __restrict__ bC,
                                                  const float* __restrict__ bD)
{
    extern __shared__ __half smem[];
    const int tid = threadIdx.x;
    const int bn = blockIdx.x, bm = blockIdx.y;
    const int tileRow = bm * TM;
    const int lane = tid & 31, wid = tid >> 5;
    const int wm = (wid & 3) * 32, wn = (wid >> 2) * 64;
    const uint32_t smb = smem_u32(smem);

    float acc[2][8][4];
#pragma unroll
    for (int a = 0; a < 2; a++)
#pragma unroll
        for (int b = 0; b < 8; b++)
#pragma unroll
            for (int c = 0; c < 4; c++) acc[a][b][c] = 0.0f;

    gemm_loop<kQ / BK>(smb, g_u16 + (size_t)tileRow * kQ,
                       g_WD16 + (size_t)bn * TN * kQ, tid, lane, wm, wn, acc);

    const int r0 = tileRow + wm + (lane >> 2);
    const int cb = bn * TN + wn;
#pragma unroll
    for (int mt = 0; mt < 2; mt++) {
        const int rr = r0 + mt * 16;
#pragma unroll
        for (int nt = 0; nt < 8; nt++) {
            const int cc = cb + nt * 8 + (lane & 3) * 2;
            const float b0 = bC[cc] + bD[cc], b1 = bC[cc + 1] + bD[cc + 1];
            uint32_t lo = packh(acc[mt][nt][0] + b0, acc[mt][nt][1] + b1);
            uint32_t hi = packh(acc[mt][nt][2] + b0, acc[mt][nt][3] + b1);
            *reinterpret_cast<uint32_t*>(&g_P16[(size_t)rr * kQ + cc]) = lo;
            *reinterpret_cast<uint32_t*>(&g_P16[(size_t)(rr + 8) * kQ + cc]) = hi;
        }
    }
}

// ---------------------------------------------------------------------------
// GEMM2: h = y16@WC16^T + P16; g=gelu(h); out = g*sigmoid(g) + u16
// ---------------------------------------------------------------------------
__global__ __launch_bounds__(256, 2) void k_mm_out(float* __restrict__ Out)
{
    extern __shared__ __half smem[];
    const int tid = threadIdx.x;
    const int bn = blockIdx.x, bm = blockIdx.y;
    const int tileRow = bm * TM;
    const int lane = tid & 31, wid = tid >> 5;
    const int wm = (wid & 3) * 32, wn = (wid >> 2) * 64;
    const uint32_t smb = smem_u32(smem);

    float acc[2][8][4];
#pragma unroll
    for (int a = 0; a < 2; a++)
#pragma unroll
        for (int b = 0; b < 8; b++)
#pragma unroll
            for (int c = 0; c < 4; c++) acc[a][b][c] = 0.0f;

    gemm_loop<kQ / BK>(smb, g_y16 + (size_t)tileRow * kQ,
                       g_WC16 + (size_t)bn * TN * kQ, tid, lane, wm, wn, acc);

    const int r0 = tileRow + wm + (lane >> 2);
    const int cbase = bn * TN + wn;
#pragma unroll
    for (int mt = 0; mt < 2; mt++) {
        const int rr = r0 + mt * 16;
#pragma unroll
        for (int nt = 0; nt < 8; nt++) {
            const int cc = cbase + nt * 8 + (lane & 3) * 2;
#pragma unroll
            for (int half = 0; half < 2; half++) {
                const int row = rr + half * 8;
                __half2 ph = *reinterpret_cast<const __half2*>(&g_P16[(size_t)row * kQ + cc]);
                float2 pv = __half22float2(ph);
                float h0 = acc[mt][nt][half * 2 + 0] + pv.x;
                float h1 = acc[mt][nt][half * 2 + 1] + pv.y;
                __half2 uh = *reinterpret_cast<const __half2*>(&g_u16[(size_t)row * kQ + cc]);
                float2 uv = __half22float2(uh);
                float g0 = 0.5f * h0 * (1.0f + erff(h0 * 0.70710678118654752f));
                float g1 = 0.5f * h1 * (1.0f + erff(h1 * 0.70710678118654752f));
                float o0 = fmaf(g0, 1.0f / (1.0f + __expf(-g0)), uv.x);
                float o1 = fmaf(g1, 1.0f / (1.0f + __expf(-g1)), uv.y);
                float2 w; w.x = o0; w.y = o1;
                *reinterpret_cast<float2*>(&Out[(size_t)row * kQ + cc]) = w;
            }
        }
    }
}

// ---------------------------------------------------------------------------
// Scan pass A: per-chunk end states — 2 channels per thread (__half2 loads)
// ---------------------------------------------------------------------------
__global__ __launch_bounds__(256) void k_scan_ends(const float* __restrict__ A)
{
    int idx = blockIdx.x * blockDim.x + threadIdx.x;   // < kB*kNChunk*kQ/2
    int q2 = idx & (kQ / 2 - 1);
    int c  = (idx >> 7) & (kNChunk - 1);
    int b  = idx >> 13;
    int qi = q2 * 2;

    float2 av = *reinterpret_cast<const float2*>(&A[qi]);
    float s0   = 1.0f / (1.0f + kDT * kDT * av.x);
    float dts0 = kDT * s0, dsa0 = dts0 * av.x;
    float s1   = 1.0f / (1.0f + kDT * kDT * av.y);
    float dts1 = kDT * s1, dsa1 = dts1 * av.y;

    const __half2* p = reinterpret_cast<const __half2*>(
        g_Bu16 + ((size_t)(b * kN + c * kCLen)) * kQ + qi);
    float x0 = 0.0f, z0 = 0.0f, x1 = 0.0f, z1 = 0.0f;
#pragma unroll 8
    for (int n = 0; n < kCLen; n++) {
        float2 bu = __half22float2(p[(size_t)n * (kQ / 2)]);
        float fx0 = dts0 * bu.x;
        float xn0 = fmaf(s0, x0, fmaf(-dsa0, z0, fx0));
        float zn0 = fmaf(dts0, x0, fmaf(s0, z0, kDT * fx0));
        x0 = xn0; z0 = zn0;
        float fx1 = dts1 * bu.y;
        float xn1 = fmaf(s1, x1, fmaf(-dsa1, z1, fx1));
        float zn1 = fmaf(dts1, x1, fmaf(s1, z1, kDT * fx1));
        x1 = xn1; z1 = zn1;
    }
    float4 o; o.x = x0; o.y = z0; o.z = x1; o.w = z1;
    *reinterpret_cast<float4*>(&g_end[(b * kNChunk + c) * kQ + qi]) = o;
}

// ---------------------------------------------------------------------------
// Scan pass B: PARALLEL chunk-prefix combine (Kogge-Stone affine scan).
// ---------------------------------------------------------------------------
__global__ __launch_bounds__(256) void k_scan_combine(const float* __restrict__ A)
{
    __shared__ float2 sb[256];
    const int tid = threadIdx.x;
    const int c = tid & (kNChunk - 1);
    const int pairIdx = blockIdx.x * 4 + (tid >> 6);
    const int qi = pairIdx & (kQ - 1);
    const int b  = pairIdx >> 8;

    float av  = A[qi];
    float s   = 1.0f / (1.0f + kDT * kDT * av);
    float dts = kDT * s;
    float dsa = dts * av;

    float p00 = s, p01 = -dsa, p10 = dts, p11 = s;
#pragma unroll
    for (int k = 0; k < 6; k++) {          // M -> M^64 = P_chunk
        float t   = p00 + p11;
        float bc  = p01 * p10;
        float n00 = fmaf(p00, p00, bc);
        float n01 = p01 * t;
        float n10 = p10 * t;
        float n11 = fmaf(p11, p11, bc);
        p00 = n00; p01 = n01; p10 = n10; p11 = n11;
    }

    const int gbase = (b * kNChunk) * kQ + qi;
    float2 v = g_end[gbase + c * kQ];

#pragma unroll
    for (int k = 0; k < 6; k++) {
        const int d = 1 << k;
        sb[tid] = v;
        __syncthreads();
        if (c >= d) {
            float2 lo = sb[tid - d];
            v.x = fmaf(p00, lo.x, fmaf(p01, lo.y, v.x));
            v.y = fmaf(p10, lo.x, fmaf(p11, lo.y, v.y));
        }
        __syncthreads();
        float t   = p00 + p11;
        float bc  = p01 * p10;
        float n00 = fmaf(p00, p00, bc);
        float n01 = p01 * t;
        float n10 = p10 * t;
        float n11 = fmaf(p11, p11, bc);
        p00 = n00; p01 = n01; p10 = n10; p11 = n11;
    }

    sb[tid] = v;
    __syncthreads();
    float2 init = (c == 0) ? make_float2(0.0f, 0.0f) : sb[tid - 1];
    g_init[gbase + c * kQ] = init;
}

// ---------------------------------------------------------------------------
// Scan pass C: re-scan chunks, emit y + y16 — 2 channels per thread
// ---------------------------------------------------------------------------
__global__ __launch_bounds__(256) void k_scan_emit(
    const float* __restrict__ A, float* __restrict__ Yout)
{
    int idx = blockIdx.x * blockDim.x + threadIdx.x;
    int q2 = idx & (kQ / 2 - 1);
    int c  = (idx >> 7) & (kNChunk - 1);
    int b  = idx >> 13;
    int qi = q2 * 2;

    float2 av = *reinterpret_cast<const float2*>(&A[qi]);
    float s0   = 1.0f / (1.0f + kDT * kDT * av.x);
    float dts0 = kDT * s0, dsa0 = dts0 * av.x;
    float s1   = 1.0f / (1.0f + kDT * kDT * av.y);
    float dts1 = kDT * s1, dsa1 = dts1 * av.y;

    size_t off = ((size_t)(b * kN + c * kCLen)) * kQ + qi;
    const __half2* p = reinterpret_cast<const __half2*>(g_Bu16 + off);
    float* yp = Yout + off;
    __half2* y16p = reinterpret_cast<__half2*>(g_y16 + off);

    float4 st = *reinterpret_cast<const float4*>(&g_init[(b * kNChunk + c) * kQ + qi]);
    float x0 = st.x, z0 = st.y, x1 = st.z, z1 = st.w;
#pragma unroll 8
    for (int n = 0; n < kCLen; n++) {
        float2 bu = __half22float2(p[(size_t)n * (kQ / 2)]);
        float fx0 = dts0 * bu.x;
        float xn0 = fmaf(s0, x0, fmaf(-dsa0, z0, fx0));
        float zn0 = fmaf(dts0, x0, fmaf(s0, z0, kDT * fx0));
        x0 = xn0; z0 = zn0;
        float fx1 = dts1 * bu.y;
        float xn1 = fmaf(s1, x1, fmaf(-dsa1, z1, fx1));
        float zn1 = fmaf(dts1, x1, fmaf(s1, z1, kDT * fx1));
        x1 = xn1; z1 = zn1;
        float2 yo; yo.x = z0; yo.y = z1;
        *reinterpret_cast<float2*>(yp + (size_t)n * kQ) = yo;
        y16p[(size_t)n * (kQ / 2)] = __floats2half2_rn(z0, z1);
    }
}

// ---------------------------------------------------------------------------
// Launch: fork k_mm_ud onto a second stream after GEMM1; it overlaps the
// scan kernels; join before k_mm_out.
// ---------------------------------------------------------------------------
extern "C" void kernel_launch(void* const* d_in, const int* in_sizes, int n_in,
                              void* d_out, int out_size)
{
    const float* u  = (const float*)d_in[0];
    const float* a  = (const float*)d_in[1];
    const float* WB = (const float*)d_in[2];
    const float* bB = (const float*)d_in[3];
    const float* WC = (const float*)d_in[4];
    const float* bC = (const float*)d_in[5];
    const float* WD = (const float*)d_in[6];
    const float* bD = (const float*)d_in[7];

    float* out  = (float*)d_out;
    float* yout = out + (size_t)out_size / 2;

    static bool init_done = false;
    static cudaStream_t s2;
    static cudaEvent_t evFork, evJoin;
    if (!init_done) {
        cudaFuncSetAttribute(k_mm_bu,  cudaFuncAttributeMaxDynamicSharedMemorySize, SMEM_BYTES);
        cudaFuncSetAttribute(k_mm_ud,  cudaFuncAttributeMaxDynamicSharedMemorySize, SMEM_BYTES);
        cudaFuncSetAttribute(k_mm_out, cudaFuncAttributeMaxDynamicSharedMemorySize, SMEM_BYTES);
        cudaStreamCreateWithFlags(&s2, cudaStreamNonBlocking);
        cudaEventCreateWithFlags(&evFork, cudaEventDisableTiming);
        cudaEventCreateWithFlags(&evJoin, cudaEventDisableTiming);
        init_done = true;
    }

    const int cvtTotal = kM * kQ / 4 + 3 * kQ * kQ / 4;
    k_cvt<<<cvtTotal / 256, 256>>>(u, WB, WC, WD);

    dim3 grid(kQ / TN, kM / TM);                // (2, 512)
    k_mm_bu<<<grid, 256, SMEM_BYTES>>>(bB);

    // fork: u@WD^T on stream 2, overlapping the scan below
    cudaEventRecord(evFork, 0);
    cudaStreamWaitEvent(s2, evFork, 0);
    k_mm_ud<<<grid, 256, SMEM_BYTES, s2>>>(bC, bD);
    cudaEventRecord(evJoin, s2);

    int scanPairs = kB * kNChunk * kQ / 2;      // 131072
    k_scan_ends<<<scanPairs / 256, 256>>>(a);
    k_scan_combine<<<(kB * kQ * kNChunk) / 256, 256>>>(a);
    k_scan_emit<<<scanPairs / 256, 256>>>(a, yout);

    // join, then final GEMM
    cudaStreamWaitEvent(0, evJoin, 0);
    k_mm_out<<<grid, 256, SMEM_BYTES>>>(out);
}

// round 16
// speedup vs baseline: 1.2115x; 1.2115x over previous
#include <cuda_runtime.h>
#include <cuda_fp16.h>
#include <math.h>
#include <stdint.h>

// ---------------------------------------------------------------------------
// LinOSS layer: B=16, N=4096, q=256 on sm_103
// fp16 operands pre-converted; GEMMs: cp.async 2-stage (BK=64) HMMA.
//   u16 = fp16(u); W*16 = fp16(W*)
//   Bu16 = fp16(u16 @ WB16^T + bB)
//   y    = IM scan over Bu16 (128 chunks of 32, KS combine); y fp32 + y16
//   h    = y16@WC16^T + u16@WD16^T + bC + bD; g=gelu(h); out=g*sigmoid(g)+u16
// Output: [out | y]
// ---------------------------------------------------------------------------

namespace {
constexpr int kB = 16;
constexpr int kN = 4096;
constexpr int kQ = 256;
constexpr int kM = kB * kN;                 // 65536
constexpr float kDT = 1.0f / 4096.0f;
constexpr int kNChunk = 128;                // chunks per sequence
constexpr int kCLen = kN / kNChunk;         // 32 (serial chain length)

constexpr int TM = 128, TN = 128, BK = 64;  // CTA tile, K-chunk (fp16)
constexpr int SSTR = 72;                    // smem row stride in halves (144 B)
constexpr int PL_ELEMS = TM * SSTR;         // 9216
constexpr int PL_BYTES = PL_ELEMS * 2;      // 18432
constexpr int STAGE_BYTES = 2 * PL_BYTES;   // 36864 (A plane + B plane)
constexpr int SMEM_BYTES = 2 * STAGE_BYTES; // 73728 (x2 CTA = 147KB, fits)
}  // namespace

// Device scratch (static; no cudaMalloc allowed)
__device__ __half g_Bu16[(size_t)kM * kQ];
__device__ float2 g_end[kB * kNChunk * kQ];
__device__ float2 g_init[kB * kNChunk * kQ];
__device__ __half g_u16[(size_t)kM * kQ];
__device__ __half g_y16[(size_t)kM * kQ];
__device__ __half g_WB16[kQ * kQ];
__device__ __half g_WC16[kQ * kQ];
__device__ __half g_WD16[kQ * kQ];

// ---------------------------------------------------------------------------
// helpers
// ---------------------------------------------------------------------------
__device__ __forceinline__ uint32_t smem_u32(const void* p) {
    uint32_t a;
    asm("{ .reg .u64 t; cvta.to.shared.u64 t, %1; cvt.u32.u64 %0, t; }" : "=r"(a) : "l"(p));
    return a;
}
__device__ __forceinline__ uint32_t packh(float a, float b) {
    __half2 h = __floats2half2_rn(a, b);
    uint32_t u; memcpy(&u, &h, 4); return u;
}
__device__ __forceinline__ void ldsm4(uint32_t (&r)[4], uint32_t addr) {
    asm volatile("ldmatrix.sync.aligned.m8n8.x4.shared.b16 {%0,%1,%2,%3}, [%4];"
                 : "=r"(r[0]), "=r"(r[1]), "=r"(r[2]), "=r"(r[3]) : "r"(addr));
}
__device__ __forceinline__ void mma16816(float* c, const uint32_t* a, const uint32_t* b) {
    asm volatile(
        "mma.sync.aligned.m16n8k16.row.col.f32.f16.f16.f32 "
        "{%0,%1,%2,%3}, {%4,%5,%6,%7}, {%8,%9}, {%0,%1,%2,%3};"
        : "+f"(c[0]), "+f"(c[1]), "+f"(c[2]), "+f"(c[3])
        : "r"(a[0]), "r"(a[1]), "r"(a[2]), "r"(a[3]), "r"(b[0]), "r"(b[1]));
}
#define CP_COMMIT() asm volatile("cp.async.commit_group;" ::: "memory")
#define CP_WAIT0()  asm volatile("cp.async.wait_group 0;" ::: "memory")

// Issue one stage: A tile (128 x 64 fp16) + B tile (128 x 64 fp16).
__device__ __forceinline__ void cpa_stage(uint32_t sb, const __half* __restrict__ aSrc,
                                          const __half* __restrict__ bSrc, int tid) {
#pragma unroll
    for (int k = 0; k < 4; k++) {
        int t = tid + k * 256;             // 0..1023
        int r = t >> 3, j = t & 7;
        const __half* g = aSrc + (size_t)r * kQ + j * 8;
        uint32_t s = sb + (uint32_t)(r * (SSTR * 2) + j * 16);
        asm volatile("cp.async.ca.shared.global [%0], [%1], 16;" :: "r"(s), "l"(g));
    }
#pragma unroll
    for (int k = 0; k < 4; k++) {
        int t = tid + k * 256;
        int r = t >> 3, j = t & 7;
        const __half* g = bSrc + (size_t)r * kQ + j * 8;
        uint32_t s = sb + PL_BYTES + (uint32_t)(r * (SSTR * 2) + j * 16);
        asm volatile("cp.async.ca.shared.global [%0], [%1], 16;" :: "r"(s), "l"(g));
    }
}

// MMA over one resident stage: warp tile 32(M) x 64(N), 4 k16 steps.
__device__ __forceinline__ void mma_stage(uint32_t sb, float (&acc)[2][8][4],
                                          int lane, int wm, int wn) {
    const int g = lane >> 3, l = lane & 7;
#pragma unroll
    for (int k16 = 0; k16 < 4; k16++) {
        uint32_t afrag[2][4];
        const int acol = k16 * 16 + (g >> 1) * 8;
#pragma unroll
        for (int mt = 0; mt < 2; mt++) {
            const int arow = wm + mt * 16 + (g & 1) * 8 + l;
            ldsm4(afrag[mt], sb + (uint32_t)(arow * SSTR + acol) * 2);
        }
        const int bcol = k16 * 16 + (g & 1) * 8;
#pragma unroll
        for (int np = 0; np < 4; np++) {
            const int brow = wn + np * 16 + (g >> 1) * 8 + l;
            uint32_t bfrag[4];
            ldsm4(bfrag, sb + PL_BYTES + (uint32_t)(brow * SSTR + bcol) * 2);
#pragma unroll
            for (int mt = 0; mt < 2; mt++) {
#pragma unroll
                for (int nt = 0; nt < 2; nt++) {
                    mma16816(acc[mt][np * 2 + nt], afrag[mt], &bfrag[nt * 2]);
                }
            }
        }
    }
}

// Shared GEMM mainloop: C chunks of BK over A/B row-major [*, kQ] sources.
template <int C>
__device__ __forceinline__ void gemm_loop(uint32_t smb, const __half* aBase,
                                          const __half* bBase, int tid, int lane,
                                          int wm, int wn, float (&acc)[2][8][4]) {
    cpa_stage(smb, aBase, bBase, tid); CP_COMMIT();
    for (int c = 0; c < C; c++) {
        CP_WAIT0();
        __syncthreads();
        if (c + 1 < C) {
            cpa_stage(smb + ((c + 1) & 1) * STAGE_BYTES,
                      aBase + (c + 1) * BK, bBase + (c + 1) * BK, tid);
            CP_COMMIT();
        }
        mma_stage(smb + (c & 1) * STAGE_BYTES, acc, lane, wm, wn);
    }
}

// ---------------------------------------------------------------------------
// Converter: u (16M elems) + WB/WC/WD (64K each), one kernel.
// ---------------------------------------------------------------------------
__global__ __launch_bounds__(256) void k_cvt(const float* __restrict__ u,
                                             const float* __restrict__ wb,
                                             const float* __restrict__ wc,
                                             const float* __restrict__ wd) {
    const int uN = kM * kQ / 4;
    const int per = kQ * kQ / 4;
    int i = blockIdx.x * blockDim.x + threadIdx.x;
    const float* s;
    __half* d;
    int j;
    if (i < uN) { s = u; d = g_u16; j = i; }
    else {
        int w = i - uN;
        s = (w < per) ? wb : (w < 2 * per ? wc : wd);
        d = (w < per) ? g_WB16 : (w < 2 * per ? g_WC16 : g_WD16);
        j = w % per;
    }
    float4 v = reinterpret_cast<const float4*>(s)[j];
    uint2 o; o.x = packh(v.x, v.y); o.y = packh(v.z, v.w);
    reinterpret_cast<uint2*>(d)[j] = o;
}

// ---------------------------------------------------------------------------
// GEMM1: g_Bu16 = fp16(u16 @ WB16^T + bias)
// ---------------------------------------------------------------------------
__global__ __launch_bounds__(256, 2) void k_mm_bu(const float* __restrict__ bias)
{
    extern __shared__ __half smem[];
    const int tid = threadIdx.x;
    const int bn = blockIdx.x, bm = blockIdx.y;
    const int tileRow = bm * TM;
    const int lane = tid & 31, wid = tid >> 5;
    const int wm = (wid & 3) * 32, wn = (wid >> 2) * 64;
    const uint32_t smb = smem_u32(smem);

    float acc[2][8][4];
#pragma unroll
    for (int a = 0; a < 2; a++)
#pragma unroll
        for (int b = 0; b < 8; b++)
#pragma unroll
            for (int c = 0; c < 4; c++) acc[a][b][c] = 0.0f;

    gemm_loop<kQ / BK>(smb, g_u16 + (size_t)tileRow * kQ,
                       g_WB16 + (size_t)bn * TN * kQ, tid, lane, wm, wn, acc);

    const int r0 = tileRow + wm + (lane >> 2);
    const int cb = bn * TN + wn;
#pragma unroll
    for (int mt = 0; mt < 2; mt++) {
        const int rr = r0 + mt * 16;
#pragma unroll
        for (int nt = 0; nt < 8; nt++) {
            const int cc = cb + nt * 8 + (lane & 3) * 2;
            const float b0 = bias[cc], b1 = bias[cc + 1];
            uint32_t lo = packh(acc[mt][nt][0] + b0, acc[mt][nt][1] + b1);
            uint32_t hi = packh(acc[mt][nt][2] + b0, acc[mt][nt][3] + b1);
            *reinterpret_cast<uint32_t*>(&g_Bu16[(size_t)rr * kQ + cc]) = lo;
            *reinterpret_cast<uint32_t*>(&g_Bu16[(size_t)(rr + 8) * kQ + cc]) = hi;
        }
    }
}

// ---------------------------------------------------------------------------
// GEMM2: h = y16@WC16^T + u16@WD16^T + bC + bD; gelu+glu epilogue,
// residual from u16.
// ---------------------------------------------------------------------------
__global__ __launch_bounds__(256, 2) void k_mm_out(
    const float* __restrict__ bC, const float* __restrict__ bD,
    float* __restrict__ Out)
{
    extern __shared__ __half smem[];
    const int tid = threadIdx.x;
    const int bn = blockIdx.x, bm = blockIdx.y;
    const int tileRow = bm * TM;
    const int lane = tid & 31, wid = tid >> 5;
    const int wm = (wid & 3) * 32, wn = (wid >> 2) * 64;
    const uint32_t smb = smem_u32(smem);

    float acc[2][8][4];
#pragma unroll
    for (int a = 0; a < 2; a++)
#pragma unroll
        for (int b = 0; b < 8; b++)
#pragma unroll
            for (int c = 0; c < 4; c++) acc[a][b][c] = 0.0f;

    constexpr int C = 2 * kQ / BK;   // 8
    auto aPtr = [&](int n) -> const __half* {
        return (n < C / 2 ? g_y16 : g_u16) + (size_t)tileRow * kQ + (n & (C / 2 - 1)) * BK;
    };
    auto bPtr = [&](int n) -> const __half* {
        return (n < C / 2 ? g_WC16 : g_WD16) + (size_t)bn * TN * kQ + (n & (C / 2 - 1)) * BK;
    };

    cpa_stage(smb, aPtr(0), bPtr(0), tid); CP_COMMIT();
    for (int c = 0; c < C; c++) {
        CP_WAIT0();
        __syncthreads();
        if (c + 1 < C) {
            cpa_stage(smb + ((c + 1) & 1) * STAGE_BYTES, aPtr(c + 1), bPtr(c + 1), tid);
            CP_COMMIT();
        }
        mma_stage(smb + (c & 1) * STAGE_BYTES, acc, lane, wm, wn);
    }

    const int r0 = tileRow + wm + (lane >> 2);
    const int cbase = bn * TN + wn;
#pragma unroll
    for (int mt = 0; mt < 2; mt++) {
        const int rr = r0 + mt * 16;
#pragma unroll
        for (int nt = 0; nt < 8; nt++) {
            const int cc = cbase + nt * 8 + (lane & 3) * 2;
            const float b0 = bC[cc] + bD[cc], b1 = bC[cc + 1] + bD[cc + 1];
#pragma unroll
            for (int half = 0; half < 2; half++) {
                const int row = rr + half * 8;
                float h0 = acc[mt][nt][half * 2 + 0] + b0;
                float h1 = acc[mt][nt][half * 2 + 1] + b1;
                __half2 uh = *reinterpret_cast<const __half2*>(&g_u16[(size_t)row * kQ + cc]);
                float2 uv = __half22float2(uh);
                float g0 = 0.5f * h0 * (1.0f + erff(h0 * 0.70710678118654752f));
                float g1 = 0.5f * h1 * (1.0f + erff(h1 * 0.70710678118654752f));
                float o0 = fmaf(g0, 1.0f / (1.0f + __expf(-g0)), uv.x);
                float o1 = fmaf(g1, 1.0f / (1.0f + __expf(-g1)), uv.y);
                float2 w; w.x = o0; w.y = o1;
                *reinterpret_cast<float2*>(&Out[(size_t)row * kQ + cc]) = w;
            }
        }
    }
}

// ---------------------------------------------------------------------------
// Scan pass A: per-chunk end states — 2 channels per thread, 32-step chains
// ---------------------------------------------------------------------------
__global__ __launch_bounds__(256) void k_scan_ends(const float* __restrict__ A)
{
    int idx = blockIdx.x * blockDim.x + threadIdx.x;   // < kB*kNChunk*kQ/2
    int q2 = idx & (kQ / 2 - 1);                       // column pair 0..127
    int c  = (idx >> 7) & (kNChunk - 1);               // chunk 0..127
    int b  = idx >> 14;
    int qi = q2 * 2;

    float2 av = *reinterpret_cast<const float2*>(&A[qi]);
    float s0   = 1.0f / (1.0f + kDT * kDT * av.x);
    float dts0 = kDT * s0, dsa0 = dts0 * av.x;
    float s1   = 1.0f / (1.0f + kDT * kDT * av.y);
    float dts1 = kDT * s1, dsa1 = dts1 * av.y;

    const __half2* p = reinterpret_cast<const __half2*>(
        g_Bu16 + ((size_t)(b * kN + c * kCLen)) * kQ + qi);
    float x0 = 0.0f, z0 = 0.0f, x1 = 0.0f, z1 = 0.0f;
#pragma unroll 8
    for (int n = 0; n < kCLen; n++) {
        float2 bu = __half22float2(p[(size_t)n * (kQ / 2)]);
        float fx0 = dts0 * bu.x;
        float xn0 = fmaf(s0, x0, fmaf(-dsa0, z0, fx0));
        float zn0 = fmaf(dts0, x0, fmaf(s0, z0, kDT * fx0));
        x0 = xn0; z0 = zn0;
        float fx1 = dts1 * bu.y;
        float xn1 = fmaf(s1, x1, fmaf(-dsa1, z1, fx1));
        float zn1 = fmaf(dts1, x1, fmaf(s1, z1, kDT * fx1));
        x1 = xn1; z1 = zn1;
    }
    float4 o; o.x = x0; o.y = z0; o.z = x1; o.w = z1;
    *reinterpret_cast<float4*>(&g_end[(b * kNChunk + c) * kQ + qi]) = o;
}

// ---------------------------------------------------------------------------
// Scan pass B: Kogge-Stone affine combine over 128 chunks.
// Per-chunk linear part P_chunk = M^kCLen (pre-squared 5x from M).
// Block = 256 threads = 2 (b,qi) pairs x 128 chunks.
// ---------------------------------------------------------------------------
__global__ __launch_bounds__(256) void k_scan_combine(const float* __restrict__ A)
{
    __shared__ float2 sb[256];
    const int tid = threadIdx.x;
    const int c = tid & (kNChunk - 1);                 // chunk 0..127
    const int pairIdx = blockIdx.x * 2 + (tid >> 7);   // (b,qi) pair
    const int qi = pairIdx & (kQ - 1);
    const int b  = pairIdx >> 8;

    float av  = A[qi];
    float s   = 1.0f / (1.0f + kDT * kDT * av);
    float dts = kDT * s;
    float dsa = dts * av;

    float p00 = s, p01 = -dsa, p10 = dts, p11 = s;
#pragma unroll
    for (int k = 0; k < 5; k++) {          // M -> M^32 = P_chunk
        float t   = p00 + p11;
        float bc  = p01 * p10;
        float n00 = fmaf(p00, p00, bc);
        float n01 = p01 * t;
        float n10 = p10 * t;
        float n11 = fmaf(p11, p11, bc);
        p00 = n00; p01 = n01; p10 = n10; p11 = n11;
    }

    const int gbase = (b * kNChunk) * kQ + qi;
    float2 v = g_end[gbase + c * kQ];

#pragma unroll
    for (int k = 0; k < 7; k++) {          // KS over 128 chunks
        const int d = 1 << k;
        sb[tid] = v;
        __syncthreads();
        if (c >= d) {
            float2 lo = sb[tid - d];
            v.x = fmaf(p00, lo.x, fmaf(p01, lo.y, v.x));
            v.y = fmaf(p10, lo.x, fmaf(p11, lo.y, v.y));
        }
        __syncthreads();
        float t   = p00 + p11;
        float bc  = p01 * p10;
        float n00 = fmaf(p00, p00, bc);
        float n01 = p01 * t;
        float n10 = p10 * t;
        float n11 = fmaf(p11, p11, bc);
        p00 = n00; p01 = n01; p10 = n10; p11 = n11;
    }

    sb[tid] = v;
    __syncthreads();
    float2 init = (c == 0) ? make_float2(0.0f, 0.0f) : sb[tid - 1];
    g_init[gbase + c * kQ] = init;
}

// ---------------------------------------------------------------------------
// Scan pass C: re-scan chunks, emit y + y16 — 2 channels per thread
// ---------------------------------------------------------------------------
__global__ __launch_bounds__(256) void k_scan_emit(
    const float* __restrict__ A, float* __restrict__ Yout)
{
    int idx = blockIdx.x * blockDim.x + threadIdx.x;
    int q2 = idx & (kQ / 2 - 1);
    int c  = (idx >> 7) & (kNChunk - 1);
    int b  = idx >> 14;
    int qi = q2 * 2;

    float2 av = *reinterpret_cast<const float2*>(&A[qi]);
    float s0   = 1.0f / (1.0f + kDT * kDT * av.x);
    float dts0 = kDT * s0, dsa0 = dts0 * av.x;
    float s1   = 1.0f / (1.0f + kDT * kDT * av.y);
    float dts1 = kDT * s1, dsa1 = dts1 * av.y;

    size_t off = ((size_t)(b * kN + c * kCLen)) * kQ + qi;
    const __half2* p = reinterpret_cast<const __half2*>(g_Bu16 + off);
    float* yp = Yout + off;
    __half2* y16p = reinterpret_cast<__half2*>(g_y16 + off);

    float4 st = *reinterpret_cast<const float4*>(&g_init[(b * kNChunk + c) * kQ + qi]);
    float x0 = st.x, z0 = st.y, x1 = st.z, z1 = st.w;
#pragma unroll 8
    for (int n = 0; n < kCLen; n++) {
        float2 bu = __half22float2(p[(size_t)n * (kQ / 2)]);
        float fx0 = dts0 * bu.x;
        float xn0 = fmaf(s0, x0, fmaf(-dsa0, z0, fx0));
        float zn0 = fmaf(dts0, x0, fmaf(s0, z0, kDT * fx0));
        x0 = xn0; z0 = zn0;
        float fx1 = dts1 * bu.y;
        float xn1 = fmaf(s1, x1, fmaf(-dsa1, z1, fx1));
        float zn1 = fmaf(dts1, x1, fmaf(s1, z1, kDT * fx1));
        x1 = xn1; z1 = zn1;
        float2 yo; yo.x = z0; yo.y = z1;
        *reinterpret_cast<float2*>(yp + (size_t)n * kQ) = yo;
        y16p[(size_t)n * (kQ / 2)] = __floats2half2_rn(z0, z1);
    }
}

// ---------------------------------------------------------------------------
// Launch
// ---------------------------------------------------------------------------
extern "C" void kernel_launch(void* const* d_in, const int* in_sizes, int n_in,
                              void* d_out, int out_size)
{
    const float* u  = (const float*)d_in[0];
    const float* a  = (const float*)d_in[1];
    const float* WB = (const float*)d_in[2];
    const float* bB = (const float*)d_in[3];
    const float* WC = (const float*)d_in[4];
    const float* bC = (const float*)d_in[5];
    const float* WD = (const float*)d_in[6];
    const float* bD = (const float*)d_in[7];

    float* out  = (float*)d_out;
    float* yout = out + (size_t)out_size / 2;

    static bool attr_done = false;
    if (!attr_done) {
        cudaFuncSetAttribute(k_mm_bu,  cudaFuncAttributeMaxDynamicSharedMemorySize, SMEM_BYTES);
        cudaFuncSetAttribute(k_mm_out, cudaFuncAttributeMaxDynamicSharedMemorySize, SMEM_BYTES);
        attr_done = true;
    }

    const int cvtTotal = kM * kQ / 4 + 3 * kQ * kQ / 4;
    k_cvt<<<cvtTotal / 256, 256>>>(u, WB, WC, WD);

    dim3 grid(kQ / TN, kM / TM);                // (2, 512)
    k_mm_bu<<<grid, 256, SMEM_BYTES>>>(bB);

    int scanPairs = kB * kNChunk * kQ / 2;      // 262144
    k_scan_ends<<<scanPairs / 256, 256>>>(a);
    k_scan_combine<<<(kB * kQ * kNChunk) / 256, 256>>>(a);   // 2048 blocks
    k_scan_emit<<<scanPairs / 256, 256>>>(a, yout);

    k_mm_out<<<grid, 256, SMEM_BYTES>>>(bC, bD, out);
}

// round 17
// speedup vs baseline: 1.2435x; 1.0263x over previous
#include <cuda_runtime.h>
#include <cuda_fp16.h>
#include <math.h>
#include <stdint.h>

// ---------------------------------------------------------------------------
// LinOSS layer: B=16, N=4096, q=256 on sm_103
// fp16 operands pre-converted; GEMMs: cp.async 2-stage (BK=64) HMMA.
//   u16 = fp16(u); W*16 = fp16(W*)
//   Bu16 = fp16(u16 @ WB16^T + bB)
//   y16  = IM scan over Bu16 (128 chunks of 32, KS combine), fp16 only
//   h    = y16@WC16^T + u16@WD16^T + bC + bD; g=gelu(h); out=g*sigmoid(g)+u16
//   (GEMM2's bn==0 CTAs also widen their resident y16 tiles to y fp32)
// Output: [out | y]
// ---------------------------------------------------------------------------

namespace {
constexpr int kB = 16;
constexpr int kN = 4096;
constexpr int kQ = 256;
constexpr int kM = kB * kN;                 // 65536
constexpr float kDT = 1.0f / 4096.0f;
constexpr int kNChunk = 128;                // chunks per sequence
constexpr int kCLen = kN / kNChunk;         // 32 (serial chain length)

constexpr int TM = 128, TN = 128, BK = 64;  // CTA tile, K-chunk (fp16)
constexpr int SSTR = 72;                    // smem row stride in halves (144 B)
constexpr int PL_ELEMS = TM * SSTR;         // 9216
constexpr int PL_BYTES = PL_ELEMS * 2;      // 18432
constexpr int STAGE_BYTES = 2 * PL_BYTES;   // 36864 (A plane + B plane)
constexpr int SMEM_BYTES = 2 * STAGE_BYTES; // 73728 (x2 CTA = 147KB, fits)
}  // namespace

// Device scratch (static; no cudaMalloc allowed)
__device__ __half g_Bu16[(size_t)kM * kQ];
__device__ float2 g_end[kB * kNChunk * kQ];
__device__ float2 g_init[kB * kNChunk * kQ];
__device__ __half g_u16[(size_t)kM * kQ];
__device__ __half g_y16[(size_t)kM * kQ];
__device__ __half g_WB16[kQ * kQ];
__device__ __half g_WC16[kQ * kQ];
__device__ __half g_WD16[kQ * kQ];

// ---------------------------------------------------------------------------
// helpers
// ---------------------------------------------------------------------------
__device__ __forceinline__ uint32_t smem_u32(const void* p) {
    uint32_t a;
    asm("{ .reg .u64 t; cvta.to.shared.u64 t, %1; cvt.u32.u64 %0, t; }" : "=r"(a) : "l"(p));
    return a;
}
__device__ __forceinline__ uint32_t packh(float a, float b) {
    __half2 h = __floats2half2_rn(a, b);
    uint32_t u; memcpy(&u, &h, 4); return u;
}
__device__ __forceinline__ void ldsm4(uint32_t (&r)[4], uint32_t addr) {
    asm volatile("ldmatrix.sync.aligned.m8n8.x4.shared.b16 {%0,%1,%2,%3}, [%4];"
                 : "=r"(r[0]), "=r"(r[1]), "=r"(r[2]), "=r"(r[3]) : "r"(addr));
}
__device__ __forceinline__ void mma16816(float* c, const uint32_t* a, const uint32_t* b) {
    asm volatile(
        "mma.sync.aligned.m16n8k16.row.col.f32.f16.f16.f32 "
        "{%0,%1,%2,%3}, {%4,%5,%6,%7}, {%8,%9}, {%0,%1,%2,%3};"
        : "+f"(c[0]), "+f"(c[1]), "+f"(c[2]), "+f"(c[3])
        : "r"(a[0]), "r"(a[1]), "r"(a[2]), "r"(a[3]), "r"(b[0]), "r"(b[1]));
}
#define CP_COMMIT() asm volatile("cp.async.commit_group;" ::: "memory")
#define CP_WAIT0()  asm volatile("cp.async.wait_group 0;" ::: "memory")

// Issue one stage: A tile (128 x 64 fp16) + B tile (128 x 64 fp16).
__device__ __forceinline__ void cpa_stage(uint32_t sb, const __half* __restrict__ aSrc,
                                          const __half* __restrict__ bSrc, int tid) {
#pragma unroll
    for (int k = 0; k < 4; k++) {
        int t = tid + k * 256;             // 0..1023
        int r = t >> 3, j = t & 7;
        const __half* g = aSrc + (size_t)r * kQ + j * 8;
        uint32_t s = sb + (uint32_t)(r * (SSTR * 2) + j * 16);
        asm volatile("cp.async.ca.shared.global [%0], [%1], 16;" :: "r"(s), "l"(g));
    }
#pragma unroll
    for (int k = 0; k < 4; k++) {
        int t = tid + k * 256;
        int r = t >> 3, j = t & 7;
        const __half* g = bSrc + (size_t)r * kQ + j * 8;
        uint32_t s = sb + PL_BYTES + (uint32_t)(r * (SSTR * 2) + j * 16);
        asm volatile("cp.async.ca.shared.global [%0], [%1], 16;" :: "r"(s), "l"(g));
    }
}

// MMA over one resident stage: warp tile 32(M) x 64(N), 4 k16 steps.
__device__ __forceinline__ void mma_stage(uint32_t sb, float (&acc)[2][8][4],
                                          int lane, int wm, int wn) {
    const int g = lane >> 3, l = lane & 7;
#pragma unroll
    for (int k16 = 0; k16 < 4; k16++) {
        uint32_t afrag[2][4];
        const int acol = k16 * 16 + (g >> 1) * 8;
#pragma unroll
        for (int mt = 0; mt < 2; mt++) {
            const int arow = wm + mt * 16 + (g & 1) * 8 + l;
            ldsm4(afrag[mt], sb + (uint32_t)(arow * SSTR + acol) * 2);
        }
        const int bcol = k16 * 16 + (g & 1) * 8;
#pragma unroll
        for (int np = 0; np < 4; np++) {
            const int brow = wn + np * 16 + (g >> 1) * 8 + l;
            uint32_t bfrag[4];
            ldsm4(bfrag, sb + PL_BYTES + (uint32_t)(brow * SSTR + bcol) * 2);
#pragma unroll
            for (int mt = 0; mt < 2; mt++) {
#pragma unroll
                for (int nt = 0; nt < 2; nt++) {
                    mma16816(acc[mt][np * 2 + nt], afrag[mt], &bfrag[nt * 2]);
                }
            }
        }
    }
}

// ---------------------------------------------------------------------------
// Converter: u (16M elems) + WB/WC/WD (64K each), one kernel.
// ---------------------------------------------------------------------------
__global__ __launch_bounds__(256) void k_cvt(const float* __restrict__ u,
                                             const float* __restrict__ wb,
                                             const float* __restrict__ wc,
                                             const float* __restrict__ wd) {
    const int uN = kM * kQ / 4;
    const int per = kQ * kQ / 4;
    int i = blockIdx.x * blockDim.x + threadIdx.x;
    const float* s;
    __half* d;
    int j;
    if (i < uN) { s = u; d = g_u16; j = i; }
    else {
        int w = i - uN;
        s = (w < per) ? wb : (w < 2 * per ? wc : wd);
        d = (w < per) ? g_WB16 : (w < 2 * per ? g_WC16 : g_WD16);
        j = w % per;
    }
    float4 v = reinterpret_cast<const float4*>(s)[j];
    uint2 o; o.x = packh(v.x, v.y); o.y = packh(v.z, v.w);
    reinterpret_cast<uint2*>(d)[j] = o;
}

// ---------------------------------------------------------------------------
// GEMM1: g_Bu16 = fp16(u16 @ WB16^T + bias)
// ---------------------------------------------------------------------------
__global__ __launch_bounds__(256, 2) void k_mm_bu(const float* __restrict__ bias)
{
    extern __shared__ __half smem[];
    const int tid = threadIdx.x;
    const int bn = blockIdx.x, bm = blockIdx.y;
    const int tileRow = bm * TM;
    const int lane = tid & 31, wid = tid >> 5;
    const int wm = (wid & 3) * 32, wn = (wid >> 2) * 64;
    const uint32_t smb = smem_u32(smem);

    float acc[2][8][4];
#pragma unroll
    for (int a = 0; a < 2; a++)
#pragma unroll
        for (int b = 0; b < 8; b++)
#pragma unroll
            for (int c = 0; c < 4; c++) acc[a][b][c] = 0.0f;

    const __half* aBase = g_u16 + (size_t)tileRow * kQ;
    const __half* bBase = g_WB16 + (size_t)bn * TN * kQ;

    cpa_stage(smb, aBase, bBase, tid); CP_COMMIT();
    constexpr int C = kQ / BK;     // 4
    for (int c = 0; c < C; c++) {
        CP_WAIT0();
        __syncthreads();
        if (c + 1 < C) {
            cpa_stage(smb + ((c + 1) & 1) * STAGE_BYTES,
                      aBase + (c + 1) * BK, bBase + (c + 1) * BK, tid);
            CP_COMMIT();
        }
        mma_stage(smb + (c & 1) * STAGE_BYTES, acc, lane, wm, wn);
    }

    const int r0 = tileRow + wm + (lane >> 2);
    const int cb = bn * TN + wn;
#pragma unroll
    for (int mt = 0; mt < 2; mt++) {
        const int rr = r0 + mt * 16;
#pragma unroll
        for (int nt = 0; nt < 8; nt++) {
            const int cc = cb + nt * 8 + (lane & 3) * 2;
            const float b0 = bias[cc], b1 = bias[cc + 1];
            uint32_t lo = packh(acc[mt][nt][0] + b0, acc[mt][nt][1] + b1);
            uint32_t hi = packh(acc[mt][nt][2] + b0, acc[mt][nt][3] + b1);
            *reinterpret_cast<uint32_t*>(&g_Bu16[(size_t)rr * kQ + cc]) = lo;
            *reinterpret_cast<uint32_t*>(&g_Bu16[(size_t)(rr + 8) * kQ + cc]) = hi;
        }
    }
}

// ---------------------------------------------------------------------------
// GEMM2: h = y16@WC16^T + u16@WD16^T + bC + bD; gelu+glu epilogue,
// residual from u16. bn==0 CTAs also widen their y16 A-stages to y fp32.
// ---------------------------------------------------------------------------
__global__ __launch_bounds__(256, 2) void k_mm_out(
    const float* __restrict__ bC, const float* __restrict__ bD,
    float* __restrict__ Out, float* __restrict__ Yout)
{
    extern __shared__ __half smem[];
    const int tid = threadIdx.x;
    const int bn = blockIdx.x, bm = blockIdx.y;
    const int tileRow = bm * TM;
    const int lane = tid & 31, wid = tid >> 5;
    const int wm = (wid & 3) * 32, wn = (wid >> 2) * 64;
    const uint32_t smb = smem_u32(smem);

    float acc[2][8][4];
#pragma unroll
    for (int a = 0; a < 2; a++)
#pragma unroll
        for (int b = 0; b < 8; b++)
#pragma unroll
            for (int c = 0; c < 4; c++) acc[a][b][c] = 0.0f;

    constexpr int C = 2 * kQ / BK;   // 8 (first 4 = y16 chunks)
    auto aPtr = [&](int n) -> const __half* {
        return (n < C / 2 ? g_y16 : g_u16) + (size_t)tileRow * kQ + (n & (C / 2 - 1)) * BK;
    };
    auto bPtr = [&](int n) -> const __half* {
        return (n < C / 2 ? g_WC16 : g_WD16) + (size_t)bn * TN * kQ + (n & (C / 2 - 1)) * BK;
    };

    cpa_stage(smb, aPtr(0), bPtr(0), tid); CP_COMMIT();
    for (int c = 0; c < C; c++) {
        CP_WAIT0();
        __syncthreads();
        if (c + 1 < C) {
            cpa_stage(smb + ((c + 1) & 1) * STAGE_BYTES, aPtr(c + 1), bPtr(c + 1), tid);
            CP_COMMIT();
        }
        mma_stage(smb + (c & 1) * STAGE_BYTES, acc, lane, wm, wn);

        // bn==0 CTAs materialize y fp32 from the resident y16 A-plane.
        // Safe: this stage buffer is only rewritten after the NEXT
        // iteration's __syncthreads (prefetch c+2 targets this buffer then).
        if (bn == 0 && c < C / 2) {
            const __half2* ap = reinterpret_cast<const __half2*>(
                smem + (size_t)(c & 1) * (STAGE_BYTES / 2));
#pragma unroll
            for (int i = 0; i < 16; i++) {
                int idx = tid + i * 256;          // 0..4095
                int r = idx >> 5;                 // row 0..127
                int j = idx & 31;                 // half2 col 0..31
                float2 fv = __half22float2(ap[r * (SSTR / 2) + j]);
                *reinterpret_cast<float2*>(
                    &Yout[(size_t)(tileRow + r) * kQ + c * BK + j * 2]) = fv;
            }
        }
    }

    const int r0 = tileRow + wm + (lane >> 2);
    const int cbase = bn * TN + wn;
#pragma unroll
    for (int mt = 0; mt < 2; mt++) {
        const int rr = r0 + mt * 16;
#pragma unroll
        for (int nt = 0; nt < 8; nt++) {
            const int cc = cbase + nt * 8 + (lane & 3) * 2;
            const float b0 = bC[cc] + bD[cc], b1 = bC[cc + 1] + bD[cc + 1];
#pragma unroll
            for (int half = 0; half < 2; half++) {
                const int row = rr + half * 8;
                float h0 = acc[mt][nt][half * 2 + 0] + b0;
                float h1 = acc[mt][nt][half * 2 + 1] + b1;
                __half2 uh = *reinterpret_cast<const __half2*>(&g_u16[(size_t)row * kQ + cc]);
                float2 uv = __half22float2(uh);
                float g0 = 0.5f * h0 * (1.0f + erff(h0 * 0.70710678118654752f));
                float g1 = 0.5f * h1 * (1.0f + erff(h1 * 0.70710678118654752f));
                float o0 = fmaf(g0, 1.0f / (1.0f + __expf(-g0)), uv.x);
                float o1 = fmaf(g1, 1.0f / (1.0f + __expf(-g1)), uv.y);
                float2 w; w.x = o0; w.y = o1;
                *reinterpret_cast<float2*>(&Out[(size_t)row * kQ + cc]) = w;
            }
        }
    }
}

// ---------------------------------------------------------------------------
// Scan pass A: per-chunk end states — 2 channels per thread, 32-step chains
// ---------------------------------------------------------------------------
__global__ __launch_bounds__(256) void k_scan_ends(const float* __restrict__ A)
{
    int idx = blockIdx.x * blockDim.x + threadIdx.x;   // < kB*kNChunk*kQ/2
    int q2 = idx & (kQ / 2 - 1);
    int c  = (idx >> 7) & (kNChunk - 1);
    int b  = idx >> 14;
    int qi = q2 * 2;

    float2 av = *reinterpret_cast<const float2*>(&A[qi]);
    float s0   = 1.0f / (1.0f + kDT * kDT * av.x);
    float dts0 = kDT * s0, dsa0 = dts0 * av.x;
    float s1   = 1.0f / (1.0f + kDT * kDT * av.y);
    float dts1 = kDT * s1, dsa1 = dts1 * av.y;

    const __half2* p = reinterpret_cast<const __half2*>(
        g_Bu16 + ((size_t)(b * kN + c * kCLen)) * kQ + qi);
    float x0 = 0.0f, z0 = 0.0f, x1 = 0.0f, z1 = 0.0f;
#pragma unroll 8
    for (int n = 0; n < kCLen; n++) {
        float2 bu = __half22float2(p[(size_t)n * (kQ / 2)]);
        float fx0 = dts0 * bu.x;
        float xn0 = fmaf(s0, x0, fmaf(-dsa0, z0, fx0));
        float zn0 = fmaf(dts0, x0, fmaf(s0, z0, kDT * fx0));
        x0 = xn0; z0 = zn0;
        float fx1 = dts1 * bu.y;
        float xn1 = fmaf(s1, x1, fmaf(-dsa1, z1, fx1));
        float zn1 = fmaf(dts1, x1, fmaf(s1, z1, kDT * fx1));
        x1 = xn1; z1 = zn1;
    }
    float4 o; o.x = x0; o.y = z0; o.z = x1; o.w = z1;
    *reinterpret_cast<float4*>(&g_end[(b * kNChunk + c) * kQ + qi]) = o;
}

// ---------------------------------------------------------------------------
// Scan pass B: Kogge-Stone affine combine over 128 chunks.
// Per-chunk linear part P_chunk = M^kCLen (pre-squared 5x from M).
// ---------------------------------------------------------------------------
__global__ __launch_bounds__(256) void k_scan_combine(const float* __restrict__ A)
{
    __shared__ float2 sb[256];
    const int tid = threadIdx.x;
    const int c = tid & (kNChunk - 1);                 // chunk 0..127
    const int pairIdx = blockIdx.x * 2 + (tid >> 7);   // (b,qi) pair
    const int qi = pairIdx & (kQ - 1);
    const int b  = pairIdx >> 8;

    float av  = A[qi];
    float s   = 1.0f / (1.0f + kDT * kDT * av);
    float dts = kDT * s;
    float dsa = dts * av;

    float p00 = s, p01 = -dsa, p10 = dts, p11 = s;
#pragma unroll
    for (int k = 0; k < 5; k++) {          // M -> M^32 = P_chunk
        float t   = p00 + p11;
        float bc  = p01 * p10;
        float n00 = fmaf(p00, p00, bc);
        float n01 = p01 * t;
        float n10 = p10 * t;
        float n11 = fmaf(p11, p11, bc);
        p00 = n00; p01 = n01; p10 = n10; p11 = n11;
    }

    const int gbase = (b * kNChunk) * kQ + qi;
    float2 v = g_end[gbase + c * kQ];

#pragma unroll
    for (int k = 0; k < 7; k++) {          // KS over 128 chunks
        const int d = 1 << k;
        sb[tid] = v;
        __syncthreads();
        if (c >= d) {
            float2 lo = sb[tid - d];
            v.x = fmaf(p00, lo.x, fmaf(p01, lo.y, v.x));
            v.y = fmaf(p10, lo.x, fmaf(p11, lo.y, v.y));
        }
        __syncthreads();
        float t   = p00 + p11;
        float bc  = p01 * p10;
        float n00 = fmaf(p00, p00, bc);
        float n01 = p01 * t;
        float n10 = p10 * t;
        float n11 = fmaf(p11, p11, bc);
        p00 = n00; p01 = n01; p10 = n10; p11 = n11;
    }

    sb[tid] = v;
    __syncthreads();
    float2 init = (c == 0) ? make_float2(0.0f, 0.0f) : sb[tid - 1];
    g_init[gbase + c * kQ] = init;
}

// ---------------------------------------------------------------------------
// Scan pass C: re-scan chunks, emit y16 only — 2 channels per thread
// ---------------------------------------------------------------------------
__global__ __launch_bounds__(256) void k_scan_emit(const float* __restrict__ A)
{
    int idx = blockIdx.x * blockDim.x + threadIdx.x;
    int q2 = idx & (kQ / 2 - 1);
    int c  = (idx >> 7) & (kNChunk - 1);
    int b  = idx >> 14;
    int qi = q2 * 2;

    float2 av = *reinterpret_cast<const float2*>(&A[qi]);
    float s0   = 1.0f / (1.0f + kDT * kDT * av.x);
    float dts0 = kDT * s0, dsa0 = dts0 * av.x;
    float s1   = 1.0f / (1.0f + kDT * kDT * av.y);
    float dts1 = kDT * s1, dsa1 = dts1 * av.y;

    size_t off = ((size_t)(b * kN + c * kCLen)) * kQ + qi;
    const __half2* p = reinterpret_cast<const __half2*>(g_Bu16 + off);
    __half2* y16p = reinterpret_cast<__half2*>(g_y16 + off);

    float4 st = *reinterpret_cast<const float4*>(&g_init[(b * kNChunk + c) * kQ + qi]);
    float x0 = st.x, z0 = st.y, x1 = st.z, z1 = st.w;
#pragma unroll 8
    for (int n = 0; n < kCLen; n++) {
        float2 bu = __half22float2(p[(size_t)n * (kQ / 2)]);
        float fx0 = dts0 * bu.x;
        float xn0 = fmaf(s0, x0, fmaf(-dsa0, z0, fx0));
        float zn0 = fmaf(dts0, x0, fmaf(s0, z0, kDT * fx0));
        x0 = xn0; z0 = zn0;
        float fx1 = dts1 * bu.y;
        float xn1 = fmaf(s1, x1, fmaf(-dsa1, z1, fx1));
        float zn1 = fmaf(dts1, x1, fmaf(s1, z1, kDT * fx1));
        x1 = xn1; z1 = zn1;
        y16p[(size_t)n * (kQ / 2)] = __floats2half2_rn(z0, z1);
    }
}

// ---------------------------------------------------------------------------
// Launch
// ---------------------------------------------------------------------------
extern "C" void kernel_launch(void* const* d_in, const int* in_sizes, int n_in,
                              void* d_out, int out_size)
{
    const float* u  = (const float*)d_in[0];
    const float* a  = (const float*)d_in[1];
    const float* WB = (const float*)d_in[2];
    const float* bB = (const float*)d_in[3];
    const float* WC = (const float*)d_in[4];
    const float* bC = (const float*)d_in[5];
    const float* WD = (const float*)d_in[6];
    const float* bD = (const float*)d_in[7];

    float* out  = (float*)d_out;
    float* yout = out + (size_t)out_size / 2;

    static bool attr_done = false;
    if (!attr_done) {
        cudaFuncSetAttribute(k_mm_bu,  cudaFuncAttributeMaxDynamicSharedMemorySize, SMEM_BYTES);
        cudaFuncSetAttribute(k_mm_out, cudaFuncAttributeMaxDynamicSharedMemorySize, SMEM_BYTES);
        attr_done = true;
    }

    const int cvtTotal = kM * kQ / 4 + 3 * kQ * kQ / 4;
    k_cvt<<<cvtTotal / 256, 256>>>(u, WB, WC, WD);

    dim3 grid(kQ / TN, kM / TM);                // (2, 512)
    k_mm_bu<<<grid, 256, SMEM_BYTES>>>(bB);

    int scanPairs = kB * kNChunk * kQ / 2;      // 262144
    k_scan_ends<<<scanPairs / 256, 256>>>(a);
    k_scan_combine<<<(kB * kQ * kNChunk) / 256, 256>>>(a);   // 2048 blocks
    k_scan_emit<<<scanPairs / 256, 256>>>(a);

    k_mm_out<<<grid, 256, SMEM_BYTES>>>(bC, bD, out, yout);
}